// round 4
// baseline (speedup 1.0000x reference)
#include <cuda_runtime.h>
#include <math_constants.h>

// CrumbReconstructor: per 8-float block of x, argmin over 256 codebook rows of
// squared L2, emit the winning row.
//
// score(j) = ||m_j||^2 - 2*k.m_j   (||k||^2 dropped: uniform in j).
// Two key-blocks per f32x2 lane-pair; codebook pre-packed in smem as
// dup(-2*m[j][c]) with dup(||m_j||^2) as the accumulator seed, so the 8
// packed FFMA2s yield both final scores directly.
//
// R3 focus: occupancy. NPAIR=2 halves key-register pressure (R1: 126 regs,
// 19.7% occ, 49.7% issue); __launch_bounds__(256,4) targets 64 regs ->
// 32 warps/SM so the FFMA2 dependency chain is latency-hidden.

#define MBLK   8
#define NCODES 256
#define TPB    256
#define NPAIR  2              // f32x2 pairs per thread
#define KPT    (2 * NPAIR)    // 4 key-blocks per thread

typedef unsigned long long u64;

__device__ __forceinline__ u64 pack2(float lo, float hi) {
    u64 r; asm("mov.b64 %0, {%1, %2};" : "=l"(r) : "f"(lo), "f"(hi)); return r;
}
__device__ __forceinline__ void unpack2(u64 v, float& lo, float& hi) {
    asm("mov.b64 {%0, %1}, %2;" : "=f"(lo), "=f"(hi) : "l"(v));
}
__device__ __forceinline__ u64 ffma2(u64 a, u64 b, u64 c) {
    u64 d; asm("fma.rn.f32x2 %0, %1, %2, %3;" : "=l"(d) : "l"(a), "l"(b), "l"(c));
    return d;
}

__global__ __launch_bounds__(TPB, 4)
void crumb_kernel(const float* __restrict__ x,
                  const float* __restrict__ mem,
                  float* __restrict__ out,
                  int nblocks)
{
    // [j][0..7] = dup(-2*m[j][c]), [j][8] = dup(||m_j||^2), [j][9] = pad
    __shared__ u64    srow[NCODES][10];
    __shared__ float4 sOrig[NCODES][2];

    const int tid = threadIdx.x;

    // ---- setup: pre-pack codebook (one row per thread; TPB == NCODES) ----
    {
        const float4* m4 = reinterpret_cast<const float4*>(mem);
        float4 a = m4[tid * 2 + 0];
        float4 b = m4[tid * 2 + 1];
        float mm = a.x*a.x + a.y*a.y + a.z*a.z + a.w*a.w
                 + b.x*b.x + b.y*b.y + b.z*b.z + b.w*b.w;
        srow[tid][0] = pack2(-2.f*a.x, -2.f*a.x);
        srow[tid][1] = pack2(-2.f*a.y, -2.f*a.y);
        srow[tid][2] = pack2(-2.f*a.z, -2.f*a.z);
        srow[tid][3] = pack2(-2.f*a.w, -2.f*a.w);
        srow[tid][4] = pack2(-2.f*b.x, -2.f*b.x);
        srow[tid][5] = pack2(-2.f*b.y, -2.f*b.y);
        srow[tid][6] = pack2(-2.f*b.z, -2.f*b.z);
        srow[tid][7] = pack2(-2.f*b.w, -2.f*b.w);
        srow[tid][8] = pack2(mm, mm);
        sOrig[tid][0] = a;
        sOrig[tid][1] = b;
    }
    __syncthreads();

    const int base = blockIdx.x * (TPB * KPT);
    const float4* x4 = reinterpret_cast<const float4*>(x);

    u64   kp[NPAIR][8];
    float bl[NPAIR], bh[NPAIR];
    int   il[NPAIR], ih[NPAIR];

    // ---- load key blocks (coalesced float4), interleave into f32x2 pairs ----
    #pragma unroll
    for (int p = 0; p < NPAIR; p++) {
        int b0 = base + (2*p + 0) * TPB + tid;
        int b1 = base + (2*p + 1) * TPB + tid;
        int c0i = (b0 < nblocks) ? b0 : 0;
        int c1i = (b1 < nblocks) ? b1 : 0;
        float4 a0 = x4[(size_t)c0i * 2 + 0], b0v = x4[(size_t)c0i * 2 + 1];
        float4 a1 = x4[(size_t)c1i * 2 + 0], b1v = x4[(size_t)c1i * 2 + 1];
        kp[p][0] = pack2(a0.x, a1.x);
        kp[p][1] = pack2(a0.y, a1.y);
        kp[p][2] = pack2(a0.z, a1.z);
        kp[p][3] = pack2(a0.w, a1.w);
        kp[p][4] = pack2(b0v.x, b1v.x);
        kp[p][5] = pack2(b0v.y, b1v.y);
        kp[p][6] = pack2(b0v.z, b1v.z);
        kp[p][7] = pack2(b0v.w, b1v.w);
        bl[p] = CUDART_INF_F; bh[p] = CUDART_INF_F;
        il[p] = 0; ih[p] = 0;
    }

    // ---- scan codes: ascending j + strict < == first-index argmin ----
    #pragma unroll 4
    for (int j = 0; j < NCODES; j++) {
        u64 c0 = srow[j][0], c1 = srow[j][1], c2 = srow[j][2], c3 = srow[j][3];
        u64 c4 = srow[j][4], c5 = srow[j][5], c6 = srow[j][6], c7 = srow[j][7];
        u64 dm = srow[j][8];
        #pragma unroll
        for (int p = 0; p < NPAIR; p++) {
            u64 d = dm;                       // seed = ||m||^2 (both halves)
            d = ffma2(kp[p][0], c0, d);
            d = ffma2(kp[p][1], c1, d);
            d = ffma2(kp[p][2], c2, d);
            d = ffma2(kp[p][3], c3, d);
            d = ffma2(kp[p][4], c4, d);
            d = ffma2(kp[p][5], c5, d);
            d = ffma2(kp[p][6], c6, d);
            d = ffma2(kp[p][7], c7, d);
            float dl, dh; unpack2(d, dl, dh);
            if (dl < bl[p]) { bl[p] = dl; il[p] = j; }
            if (dh < bh[p]) { bh[p] = dh; ih[p] = j; }
        }
    }

    // ---- gather winning rows, coalesced float4 stores ----
    float4* o4 = reinterpret_cast<float4*>(out);
    #pragma unroll
    for (int p = 0; p < NPAIR; p++) {
        int b0 = base + (2*p + 0) * TPB + tid;
        int b1 = base + (2*p + 1) * TPB + tid;
        if (b0 < nblocks) {
            o4[(size_t)b0 * 2 + 0] = sOrig[il[p]][0];
            o4[(size_t)b0 * 2 + 1] = sOrig[il[p]][1];
        }
        if (b1 < nblocks) {
            o4[(size_t)b1 * 2 + 0] = sOrig[ih[p]][0];
            o4[(size_t)b1 * 2 + 1] = sOrig[ih[p]][1];
        }
    }
}

extern "C" void kernel_launch(void* const* d_in, const int* in_sizes, int n_in,
                              void* d_out, int out_size)
{
    const float* x   = (const float*)d_in[0];
    const float* mem = (const float*)d_in[1];
    float* out = (float*)d_out;

    int nblocks = in_sizes[0] / MBLK;                 // 802816
    int per_cta = TPB * KPT;                          // 1024
    int grid = (nblocks + per_cta - 1) / per_cta;     // 784

    crumb_kernel<<<grid, TPB>>>(x, mem, out, nblocks);
}

// round 5
// speedup vs baseline: 1.4498x; 1.4498x over previous
#include <cuda_runtime.h>
#include <math_constants.h>

// CrumbReconstructor: per 8-float block of x, argmin over 256 codebook rows of
// squared L2, emit the winning row.
//
// score(j) = ||m_j||^2 - 2*k.m_j   (||k||^2 dropped: uniform in j).
//
// R4: f32x2 pairs TWO CODES (j, j+1) per lane-pair. Keys are dup-packed once
// at load; codebook smem is pair-interleaved so each code-pair costs only
// 4x LDS.128 + 1x LDS.64 (fixes R3's LDS/MIO bottleneck). 8 FFMA2 produce
// both codes' final scores (seed = (mm_j, mm_j+1)).

#define MBLK   8
#define NCODES 256
#define NJP    (NCODES / 2)   // 128 code pairs
#define TPB    128
#define KPT    4              // key-blocks per thread

typedef unsigned long long u64;

__device__ __forceinline__ u64 pack2(float lo, float hi) {
    u64 r; asm("mov.b64 %0, {%1, %2};" : "=l"(r) : "f"(lo), "f"(hi)); return r;
}
__device__ __forceinline__ void unpack2(u64 v, float& lo, float& hi) {
    asm("mov.b64 {%0, %1}, %2;" : "=f"(lo), "=f"(hi) : "l"(v));
}
__device__ __forceinline__ u64 ffma2(u64 a, u64 b, u64 c) {
    u64 d; asm("fma.rn.f32x2 %0, %1, %2, %3;" : "=l"(d) : "l"(a), "l"(b), "l"(c));
    return d;
}

__global__ __launch_bounds__(TPB, 4)
void crumb_kernel(const float* __restrict__ x,
                  const float* __restrict__ mem,
                  float* __restrict__ out,
                  int nblocks)
{
    // Pair-interleaved codebook: row jp (stride 80B = 5x16B, keeps 16B align):
    //   u64[c] = (-2*m[2jp][c], -2*m[2jp+1][c])  c=0..7
    //   u64[8] = (||m_2jp||^2, ||m_2jp+1||^2)
    __shared__ __align__(16) u64 spair[NJP][10];
    __shared__ float4 sOrig[NCODES][2];

    const int tid = threadIdx.x;

    // ---- setup: scatter codebook into pair-interleaved layout ----
    for (int j = tid; j < NCODES; j += TPB) {
        const float4* m4 = reinterpret_cast<const float4*>(mem);
        float4 a = m4[j * 2 + 0];
        float4 b = m4[j * 2 + 1];
        float mm = a.x*a.x + a.y*a.y + a.z*a.z + a.w*a.w
                 + b.x*b.x + b.y*b.y + b.z*b.z + b.w*b.w;
        float* sp = reinterpret_cast<float*>(&spair[j >> 1][0]);
        int h = j & 1;                    // lo half = even j (first index)
        sp[0*2 + h] = -2.f * a.x;
        sp[1*2 + h] = -2.f * a.y;
        sp[2*2 + h] = -2.f * a.z;
        sp[3*2 + h] = -2.f * a.w;
        sp[4*2 + h] = -2.f * b.x;
        sp[5*2 + h] = -2.f * b.y;
        sp[6*2 + h] = -2.f * b.z;
        sp[7*2 + h] = -2.f * b.w;
        sp[8*2 + h] = mm;
        sOrig[j][0] = a;
        sOrig[j][1] = b;
    }
    __syncthreads();

    const int base = blockIdx.x * (TPB * KPT);
    const float4* x4 = reinterpret_cast<const float4*>(x);

    u64   kp[KPT][8];          // dup-packed key components
    float best[KPT];
    int   idx[KPT];

    // ---- load keys (coalesced float4), duplicate into f32x2 halves ----
    #pragma unroll
    for (int p = 0; p < KPT; p++) {
        int b = base + p * TPB + tid;
        int bb = (b < nblocks) ? b : 0;
        float4 a = x4[(size_t)bb * 2 + 0];
        float4 v = x4[(size_t)bb * 2 + 1];
        kp[p][0] = pack2(a.x, a.x);
        kp[p][1] = pack2(a.y, a.y);
        kp[p][2] = pack2(a.z, a.z);
        kp[p][3] = pack2(a.w, a.w);
        kp[p][4] = pack2(v.x, v.x);
        kp[p][5] = pack2(v.y, v.y);
        kp[p][6] = pack2(v.z, v.z);
        kp[p][7] = pack2(v.w, v.w);
        best[p] = CUDART_INF_F;
        idx[p]  = 0;
    }

    // ---- scan code pairs; within-pair lo-first + strict < across pairs
    //      reproduces argmin first-index tie-break exactly ----
    #pragma unroll 2
    for (int jp = 0; jp < NJP; jp++) {
        const ulonglong2* row = reinterpret_cast<const ulonglong2*>(&spair[jp][0]);
        ulonglong2 q0 = row[0];   // c0, c1
        ulonglong2 q1 = row[1];   // c2, c3
        ulonglong2 q2 = row[2];   // c4, c5
        ulonglong2 q3 = row[3];   // c6, c7
        u64 mmp = spair[jp][8];

        #pragma unroll
        for (int p = 0; p < KPT; p++) {
            u64 d = mmp;                      // seed = (mm_j, mm_j+1)
            d = ffma2(kp[p][0], q0.x, d);
            d = ffma2(kp[p][1], q0.y, d);
            d = ffma2(kp[p][2], q1.x, d);
            d = ffma2(kp[p][3], q1.y, d);
            d = ffma2(kp[p][4], q2.x, d);
            d = ffma2(kp[p][5], q2.y, d);
            d = ffma2(kp[p][6], q3.x, d);
            d = ffma2(kp[p][7], q3.y, d);
            float dl, dh; unpack2(d, dl, dh);
            float m  = fminf(dl, dh);
            int   js = (jp << 1) + ((dl <= dh) ? 0 : 1);
            if (m < best[p]) { best[p] = m; idx[p] = js; }
        }
    }

    // ---- gather winning rows, coalesced float4 stores ----
    float4* o4 = reinterpret_cast<float4*>(out);
    #pragma unroll
    for (int p = 0; p < KPT; p++) {
        int b = base + p * TPB + tid;
        if (b < nblocks) {
            o4[(size_t)b * 2 + 0] = sOrig[idx[p]][0];
            o4[(size_t)b * 2 + 1] = sOrig[idx[p]][1];
        }
    }
}

extern "C" void kernel_launch(void* const* d_in, const int* in_sizes, int n_in,
                              void* d_out, int out_size)
{
    const float* x   = (const float*)d_in[0];
    const float* mem = (const float*)d_in[1];
    float* out = (float*)d_out;

    int nblocks = in_sizes[0] / MBLK;                 // 802816
    int per_cta = TPB * KPT;                          // 512
    int grid = (nblocks + per_cta - 1) / per_cta;     // 1568

    crumb_kernel<<<grid, TPB>>>(x, mem, out, nblocks);
}